// round 16
// baseline (speedup 1.0000x reference)
#include <cuda_runtime.h>
#include <cstdint>

// ---------------------------------------------------------------------------
// PartBasedGraphCNN: conv3x3(3->32)+relu+pool2 -> grid-GCN(32->64) -> FC1 -> FC2
// R16 = R15 (best) + reduce regridded to 256 blocks + fc1 fully unrolled.
// ---------------------------------------------------------------------------

#define K_FC 262144  // 4096 nodes * 64 feats

__device__ float d_pool_buf[32 * 32 * 64 * 64];       // [B][32][64][64] 16.8 MB
__device__ uint16_t d_g_hi[32u * 262144u];            // [B][K] bf16 hi  16.8 MB
__device__ uint16_t d_g_lo[32u * 262144u];            // [B][K] bf16 lo  16.8 MB
__device__ float d_part_buf[1024 * 32 * 128];         // [set][B][128]   16.8 MB
__device__ float d_f1_buf[32 * 128];                  // [B][128]

__device__ __forceinline__ void fma2(float2 &d, const float2 a, const float2 b) {
    asm("fma.rn.f32x2 %0, %1, %2, %0;"
        : "+l"(*reinterpret_cast<unsigned long long *>(&d))
        : "l"(*reinterpret_cast<const unsigned long long *>(&a)),
          "l"(*reinterpret_cast<const unsigned long long *>(&b)));
}

__device__ __forceinline__ uint32_t s2u(const void *p) {
    return (uint32_t)__cvta_generic_to_shared(p);
}

__device__ __forceinline__ void bulk_cp(uint32_t dst_smem, const void *src_gmem,
                                        uint32_t bytes, uint32_t mbar) {
    asm volatile(
        "cp.async.bulk.shared::cta.global.mbarrier::complete_tx::bytes "
        "[%0], [%1], %2, [%3];"
        :: "r"(dst_smem), "l"(src_gmem), "r"(bytes), "r"(mbar) : "memory");
}

__device__ __forceinline__ void mbar_init(uint32_t mbar, uint32_t count) {
    asm volatile("mbarrier.init.shared::cta.b64 [%0], %1;" :: "r"(mbar), "r"(count));
}

__device__ __forceinline__ void mbar_expect_tx(uint32_t mbar, uint32_t bytes) {
    asm volatile("mbarrier.arrive.expect_tx.shared::cta.b64 _, [%0], %1;"
                 :: "r"(mbar), "r"(bytes) : "memory");
}

__device__ __forceinline__ void mbar_wait(uint32_t mbar, uint32_t parity) {
    asm volatile(
        "{\n\t"
        ".reg .pred P;\n\t"
        "WAIT_%=:\n\t"
        "mbarrier.try_wait.parity.acquire.cta.shared::cta.b64 P, [%0], %1, 0x989680;\n\t"
        "@P bra.uni DONE_%=;\n\t"
        "bra.uni WAIT_%=;\n\t"
        "DONE_%=:\n\t"
        "}"
        :: "r"(mbar), "r"(parity) : "memory");
}

// fp32 pair -> bf16x2 hi + bf16x2 lo (residual). lo half of reg = even elem.
__device__ __forceinline__ void cvt_hilo(float2 f, uint32_t &hi, uint32_t &lo) {
    asm("cvt.rn.bf16x2.f32 %0, %1, %2;" : "=r"(hi) : "f"(f.y), "f"(f.x));
    float rx = f.x - __uint_as_float(hi << 16);
    float ry = f.y - __uint_as_float(hi & 0xFFFF0000u);
    asm("cvt.rn.bf16x2.f32 %0, %1, %2;" : "=r"(lo) : "f"(ry), "f"(rx));
}

// m16n8k16 row.col bf16 HMMA, D=C in-place
__device__ __forceinline__ void mma_bf16(float *d, const uint32_t *a,
                                         const uint32_t *b) {
    asm volatile(
        "mma.sync.aligned.m16n8k16.row.col.f32.bf16.bf16.f32 "
        "{%0,%1,%2,%3}, {%4,%5,%6,%7}, {%8,%9}, {%0,%1,%2,%3};"
        : "+f"(d[0]), "+f"(d[1]), "+f"(d[2]), "+f"(d[3])
        : "r"(a[0]), "r"(a[1]), "r"(a[2]), "r"(a[3]), "r"(b[0]), "r"(b[1]));
}

// ---------------------------------------------------------------------------
// Kernel 1: conv 3x3 SAME + bias + relu + maxpool 2x2 (R13/R15 proven).
// ---------------------------------------------------------------------------
__global__ void __launch_bounds__(256) conv_pool_kernel(
    const float *__restrict__ x, const float *__restrict__ cw,
    const float *__restrict__ cb)
{
    __shared__ float sin_[3][34][34];
    __shared__ float wp[27 * 32];
    __shared__ float bb[32];

    int t = threadIdx.x;
    int b = blockIdx.y;
    int tpy = (blockIdx.x >> 2) * 16, tpx = (blockIdx.x & 3) * 16;

    for (int i = t; i < 864; i += 256) {
        int co = i / 27, rem = i % 27;
        wp[rem * 32 + co] = cw[i];
    }
    if (t < 32) bb[t] = cb[t];

    int oy = 2 * tpy - 1, ox = 2 * tpx - 1;
    for (int i = t; i < 3 * 34 * 34; i += 256) {
        int ci = i / 1156, rem = i % 1156, iy = rem / 34, ix = rem % 34;
        int gy = oy + iy, gx = ox + ix;
        float v = 0.f;
        if (gy >= 0 && gy < 128 && gx >= 0 && gx < 128)
            v = x[((b * 3 + ci) * 128 + gy) * 128 + gx];
        sin_[ci][iy][ix] = v;
    }
    __syncthreads();

    int py = t >> 4, px = t & 15;
    float in[3][4][4];
#pragma unroll
    for (int ci = 0; ci < 3; ci++)
#pragma unroll
        for (int r = 0; r < 4; r++)
#pragma unroll
            for (int c = 0; c < 4; c++)
                in[ci][r][c] = sin_[ci][2 * py + r][2 * px + c];

    const float2 *wp2 = reinterpret_cast<const float2 *>(wp);
    int gy = tpy + py, gx = tpx + px;
    float *outb = d_pool_buf + (size_t)b * 131072;

#pragma unroll
    for (int g = 0; g < 4; g++) {
        float2 acc[2][2][4];
#pragma unroll
        for (int dy = 0; dy < 2; dy++)
#pragma unroll
            for (int dx = 0; dx < 2; dx++)
#pragma unroll
                for (int p = 0; p < 4; p++) acc[dy][dx][p] = make_float2(0.f, 0.f);

#pragma unroll
        for (int ci = 0; ci < 3; ci++)
#pragma unroll
            for (int ky = 0; ky < 3; ky++)
#pragma unroll
                for (int kx = 0; kx < 3; kx++) {
                    int tap = ci * 9 + ky * 3 + kx;
                    float2 w0 = wp2[tap * 16 + g * 4 + 0];
                    float2 w1 = wp2[tap * 16 + g * 4 + 1];
                    float2 w2 = wp2[tap * 16 + g * 4 + 2];
                    float2 w3 = wp2[tap * 16 + g * 4 + 3];
#pragma unroll
                    for (int dy = 0; dy < 2; dy++)
#pragma unroll
                        for (int dx = 0; dx < 2; dx++) {
                            float iv = in[ci][dy + ky][dx + kx];
                            float2 iv2 = make_float2(iv, iv);
                            fma2(acc[dy][dx][0], iv2, w0);
                            fma2(acc[dy][dx][1], iv2, w1);
                            fma2(acc[dy][dx][2], iv2, w2);
                            fma2(acc[dy][dx][3], iv2, w3);
                        }
                }
#pragma unroll
        for (int p = 0; p < 4; p++) {
            int co = g * 8 + p * 2;
            float mx = fmaxf(fmaxf(acc[0][0][p].x, acc[0][1][p].x),
                             fmaxf(acc[1][0][p].x, acc[1][1][p].x));
            float my = fmaxf(fmaxf(acc[0][0][p].y, acc[0][1][p].y),
                             fmaxf(acc[1][0][p].y, acc[1][1][p].y));
            mx = fmaxf(mx + bb[co], 0.f);
            my = fmaxf(my + bb[co + 1], 0.f);
            outb[(co * 64 + gy) * 64 + gx] = mx;
            outb[((co + 1) * 64 + gy) * 64 + gx] = my;
        }
    }
}

// ---------------------------------------------------------------------------
// Kernel 2: GCN (R13/R15: node chunk 256, smem 45KB, 3 CTAs/SM).
// ---------------------------------------------------------------------------
__device__ __forceinline__ float dinvf(int r, int c) {
    int deg = 1 + (r > 0) + (r < 63) + (c > 0) + (c < 63);
    return rsqrtf((float)deg);
}

__global__ void __launch_bounds__(256) gcn_kernel(
    const float *__restrict__ gw, const float *__restrict__ gb)
{
    extern __shared__ float sm[];
    float *aggx = sm;            // [256][36]
    float *wg = sm + 256 * 36;   // [32][64]
    float *bg = wg + 2048;       // [64]

    int t = threadIdx.x, b = blockIdx.y;
    int node0 = blockIdx.x * 256;

    for (int i = t; i < 2048; i += 256) wg[i] = gw[i];
    if (t < 64) bg[t] = gb[t];

    const float *nf = d_pool_buf + (size_t)b * 131072;
    int q = t & 7, ns = t >> 3;
#pragma unroll 4
    for (int i = 0; i < 8; i++) {
        int nl = ns + 32 * i;
        int n = node0 + nl;
        int r = n >> 6, c = n & 63;
        float dn = dinvf(r, c);
        const float4 *base = reinterpret_cast<const float4 *>(nf) + n * 8 + q;
        float4 v = __ldg(base);
        float4 a;
        a.x = dn * v.x; a.y = dn * v.y; a.z = dn * v.z; a.w = dn * v.w;
        if (r > 0) {
            float s = dinvf(r - 1, c); float4 u = __ldg(base - 512);
            a.x += s * u.x; a.y += s * u.y; a.z += s * u.z; a.w += s * u.w;
        }
        if (r < 63) {
            float s = dinvf(r + 1, c); float4 u = __ldg(base + 512);
            a.x += s * u.x; a.y += s * u.y; a.z += s * u.z; a.w += s * u.w;
        }
        if (c > 0) {
            float s = dinvf(r, c - 1); float4 u = __ldg(base - 8);
            a.x += s * u.x; a.y += s * u.y; a.z += s * u.z; a.w += s * u.w;
        }
        if (c < 63) {
            float s = dinvf(r, c + 1); float4 u = __ldg(base + 8);
            a.x += s * u.x; a.y += s * u.y; a.z += s * u.z; a.w += s * u.w;
        }
        a.x *= dn; a.y *= dn; a.z *= dn; a.w *= dn;
        *reinterpret_cast<float4 *>(&aggx[nl * 36 + q * 4]) = a;
    }
    __syncthreads();

    int ot = t & 7, ng = t >> 3;
    const float4 *wg4 = reinterpret_cast<const float4 *>(wg);
    uint32_t *ghi = reinterpret_cast<uint32_t *>(d_g_hi) + (size_t)b * 131072;
    uint32_t *glo = reinterpret_cast<uint32_t *>(d_g_lo) + (size_t)b * 131072;

    for (int it = 0; it < 2; it++) {
        int nb = (it * 32 + ng) * 4;
        float2 acc[4][4];
#pragma unroll
        for (int i = 0; i < 4; i++)
#pragma unroll
            for (int p = 0; p < 4; p++) acc[i][p] = make_float2(0.f, 0.f);

#pragma unroll 4
        for (int f = 0; f < 32; f++) {
            float4 wA = wg4[f * 16 + ot * 2];
            float4 wB = wg4[f * 16 + ot * 2 + 1];
            float2 p0 = make_float2(wA.x, wA.y), p1 = make_float2(wA.z, wA.w);
            float2 p2 = make_float2(wB.x, wB.y), p3 = make_float2(wB.z, wB.w);
#pragma unroll
            for (int i = 0; i < 4; i++) {
                float av = aggx[(nb + i) * 36 + f];
                float2 ad = make_float2(av, av);
                fma2(acc[i][0], ad, p0);
                fma2(acc[i][1], ad, p1);
                fma2(acc[i][2], ad, p2);
                fma2(acc[i][3], ad, p3);
            }
        }

#pragma unroll
        for (int i = 0; i < 4; i++) {
            int ubase = (node0 + nb + i) * 32 + ot * 4;
            uint4 H, L;
            float2 v;
            v.x = fmaxf(acc[i][0].x + bg[ot * 8 + 0], 0.f);
            v.y = fmaxf(acc[i][0].y + bg[ot * 8 + 1], 0.f);
            cvt_hilo(v, H.x, L.x);
            v.x = fmaxf(acc[i][1].x + bg[ot * 8 + 2], 0.f);
            v.y = fmaxf(acc[i][1].y + bg[ot * 8 + 3], 0.f);
            cvt_hilo(v, H.y, L.y);
            v.x = fmaxf(acc[i][2].x + bg[ot * 8 + 4], 0.f);
            v.y = fmaxf(acc[i][2].y + bg[ot * 8 + 5], 0.f);
            cvt_hilo(v, H.z, L.z);
            v.x = fmaxf(acc[i][3].x + bg[ot * 8 + 6], 0.f);
            v.y = fmaxf(acc[i][3].y + bg[ot * 8 + 7], 0.f);
            cvt_hilo(v, H.w, L.w);
            *reinterpret_cast<uint4 *>(ghi + ubase) = H;
            *reinterpret_cast<uint4 *>(glo + ubase) = L;
        }
    }
}

// ---------------------------------------------------------------------------
// Kernel 3: FC1 streaming HMMA GEMM (R13 config; inner loop fully unrolled).
// ---------------------------------------------------------------------------
#define FC1_KSLICE 256
#define GROW_U32 132                     // uint32 words per padded G row (4 mod 32)
#define G_LO_OFF (32 * GROW_U32)         // uint32 offset of lo plane
#define FC1_SMEM (2 * 32 * GROW_U32 * 4 + 16)  // 33808 B

__global__ void __launch_bounds__(256) fc1_kernel(const float *__restrict__ w1)
{
    extern __shared__ uint32_t smg[];
    uint32_t sb = s2u(smg);
    uint32_t mb = sb + 2 * 32 * GROW_U32 * 4;
    int t = threadIdx.x, lane = t & 31, w = t >> 5;
    int bi = blockIdx.x;
    int kstart = bi * FC1_KSLICE;

    if (t == 0) mbar_init(mb, 32);
    __syncthreads();
    if (t < 32) {
        mbar_expect_tx(mb, 2 * FC1_KSLICE * 2);
        bulk_cp(sb + lane * (GROW_U32 * 4),
                d_g_hi + (size_t)lane * K_FC + kstart, FC1_KSLICE * 2, mb);
        bulk_cp(sb + G_LO_OFF * 4 + lane * (GROW_U32 * 4),
                d_g_lo + (size_t)lane * K_FC + kstart, FC1_KSLICE * 2, mb);
    }
    mbar_wait(mb, 0);

    float acc[4][4];
#pragma unroll
    for (int nt = 0; nt < 4; nt++)
#pragma unroll
        for (int p = 0; p < 4; p++) acc[nt][p] = 0.f;

    int q = lane >> 2, kc2 = lane & 3;   // fragment coords; kc = 2*kc2
    int mbase = 16 * w;
    const float *wb0 = w1 + (size_t)(mbase + q) * K_FC + kstart + kc2 * 2;
    const float *wb1 = wb0 + (size_t)8 * K_FC;

#pragma unroll
    for (int ks = 0; ks < FC1_KSLICE / 16; ks++) {
        float2 fa0 = __ldg(reinterpret_cast<const float2 *>(wb0 + ks * 16));
        float2 fa1 = __ldg(reinterpret_cast<const float2 *>(wb1 + ks * 16));
        float2 fa2 = __ldg(reinterpret_cast<const float2 *>(wb0 + ks * 16 + 8));
        float2 fa3 = __ldg(reinterpret_cast<const float2 *>(wb1 + ks * 16 + 8));
        uint32_t Ah[4], Al[4];
        cvt_hilo(fa0, Ah[0], Al[0]);
        cvt_hilo(fa1, Ah[1], Al[1]);
        cvt_hilo(fa2, Ah[2], Al[2]);
        cvt_hilo(fa3, Ah[3], Al[3]);

        int wq = ks * 8 + kc2;
#pragma unroll
        for (int nt = 0; nt < 4; nt++) {
            int n = nt * 8 + q;
            uint32_t bh[2], bl[2];
            bh[0] = smg[n * GROW_U32 + wq];
            bh[1] = smg[n * GROW_U32 + wq + 4];
            bl[0] = smg[G_LO_OFF + n * GROW_U32 + wq];
            bl[1] = smg[G_LO_OFF + n * GROW_U32 + wq + 4];
            mma_bf16(acc[nt], Ah, bh);
            mma_bf16(acc[nt], Ah, bl);
            mma_bf16(acc[nt], Al, bh);
        }
    }

    float *pp = d_part_buf + (size_t)bi * 4096;
    int cb = kc2 * 2;
#pragma unroll
    for (int nt = 0; nt < 4; nt++) {
        int n0 = nt * 8 + cb;
        pp[(n0    ) * 128 + mbase + q    ] = acc[nt][0];
        pp[(n0 + 1) * 128 + mbase + q    ] = acc[nt][1];
        pp[(n0    ) * 128 + mbase + q + 8] = acc[nt][2];
        pp[(n0 + 1) * 128 + mbase + q + 8] = acc[nt][3];
    }
}

// ---------------------------------------------------------------------------
// Kernel 4a: reduce 1024 partial sets -> relu(f1 + b1).
// grid (32 b, 8 jq) = 256 blocks; 512 threads = 16 j x 32 set-groups;
// each thread sums 32 sets (fully unrolled).
// ---------------------------------------------------------------------------
__global__ void __launch_bounds__(512) fc1_reduce_kernel(const float *__restrict__ f1b)
{
    __shared__ float red[32][17];
    int t = threadIdx.x, b = blockIdx.x, jq = blockIdx.y;
    int jl = t & 15, sg = t >> 4;
    int j = jq * 16 + jl;

    const float *pp = d_part_buf + b * 128 + j;
    float ssum = 0.f;
#pragma unroll
    for (int i = 0; i < 32; i++)
        ssum += __ldg(&pp[(size_t)(sg + 32 * i) * 4096]);
    red[sg][jl] = ssum;
    __syncthreads();

    if (t < 16) {
        float v = 0.f;
#pragma unroll
        for (int u = 0; u < 32; u++) v += red[u][t];
        int jo = jq * 16 + t;
        d_f1_buf[b * 128 + jo] = fmaxf(v + f1b[jo], 0.f);
    }
}

// ---------------------------------------------------------------------------
// Kernel 4b: FC2 (101 x 128) + bias.  grid 32 (one block per batch)
// ---------------------------------------------------------------------------
__global__ void __launch_bounds__(128) fc2_kernel(
    const float *__restrict__ w2, const float *__restrict__ b2,
    float *__restrict__ out)
{
    __shared__ float f1s[128];
    int t = threadIdx.x, b = blockIdx.x;
    f1s[t] = d_f1_buf[b * 128 + t];
    __syncthreads();

    if (t < 101) {
        float acc = b2[t];
        const float *wr = w2 + t * 128;
#pragma unroll 8
        for (int jj = 0; jj < 128; jj++) acc = fmaf(f1s[jj], __ldg(&wr[jj]), acc);
        out[b * 101 + t] = acc;
    }
}

// ---------------------------------------------------------------------------
extern "C" void kernel_launch(void *const *d_in, const int *in_sizes, int n_in,
                              void *d_out, int out_size)
{
    (void)in_sizes; (void)n_in; (void)out_size;
    const float *x  = (const float *)d_in[0];
    const float *cw = (const float *)d_in[1];
    const float *cb = (const float *)d_in[2];
    const float *gw = (const float *)d_in[3];
    const float *gb = (const float *)d_in[4];
    const float *w1 = (const float *)d_in[5];
    const float *b1 = (const float *)d_in[6];
    const float *w2 = (const float *)d_in[7];
    const float *b2 = (const float *)d_in[8];
    float *out = (float *)d_out;

    const int gcn_smem = (256 * 36 + 2048 + 64) * 4;  // 45312 B
    cudaFuncSetAttribute(gcn_kernel, cudaFuncAttributeMaxDynamicSharedMemorySize, gcn_smem);
    cudaFuncSetAttribute(fc1_kernel, cudaFuncAttributeMaxDynamicSharedMemorySize, FC1_SMEM);

    conv_pool_kernel<<<dim3(16, 32), 256>>>(x, cw, cb);    // launch 1
    gcn_kernel<<<dim3(16, 32), 256, gcn_smem>>>(gw, gb);   // launch 2
    fc1_kernel<<<1024, 256, FC1_SMEM>>>(w1);               // launch 3
    fc1_reduce_kernel<<<dim3(32, 8), 512>>>(b1);           // launch 4 <- ncu target
    fc2_kernel<<<32, 128>>>(w2, b2, out);                  // launch 5
}

// round 17
// speedup vs baseline: 1.0489x; 1.0489x over previous
#include <cuda_runtime.h>
#include <cstdint>

// ---------------------------------------------------------------------------
// PartBasedGraphCNN: conv3x3(3->32)+relu+pool2 -> grid-GCN(32->64) -> FC1 -> FC2
// R17 = R15 (proven 128.0us config) + PDL (programmatic dependent launch) on
// launches 2-5 to hide ~2.5us/boundary launch latency (4 boundaries).
// ---------------------------------------------------------------------------

#define K_FC 262144  // 4096 nodes * 64 feats

__device__ float d_pool_buf[32 * 32 * 64 * 64];       // [B][32][64][64] 16.8 MB
__device__ uint16_t d_g_hi[32u * 262144u];            // [B][K] bf16 hi  16.8 MB
__device__ uint16_t d_g_lo[32u * 262144u];            // [B][K] bf16 lo  16.8 MB
__device__ float d_part_buf[1024 * 32 * 128];         // [set][B][128]   16.8 MB
__device__ float d_f1_buf[32 * 128];                  // [B][128]

__device__ __forceinline__ void grid_dep_wait() {
    asm volatile("griddepcontrol.wait;" ::: "memory");
}

__device__ __forceinline__ void fma2(float2 &d, const float2 a, const float2 b) {
    asm("fma.rn.f32x2 %0, %1, %2, %0;"
        : "+l"(*reinterpret_cast<unsigned long long *>(&d))
        : "l"(*reinterpret_cast<const unsigned long long *>(&a)),
          "l"(*reinterpret_cast<const unsigned long long *>(&b)));
}

__device__ __forceinline__ uint32_t s2u(const void *p) {
    return (uint32_t)__cvta_generic_to_shared(p);
}

__device__ __forceinline__ void bulk_cp(uint32_t dst_smem, const void *src_gmem,
                                        uint32_t bytes, uint32_t mbar) {
    asm volatile(
        "cp.async.bulk.shared::cta.global.mbarrier::complete_tx::bytes "
        "[%0], [%1], %2, [%3];"
        :: "r"(dst_smem), "l"(src_gmem), "r"(bytes), "r"(mbar) : "memory");
}

__device__ __forceinline__ void mbar_init(uint32_t mbar, uint32_t count) {
    asm volatile("mbarrier.init.shared::cta.b64 [%0], %1;" :: "r"(mbar), "r"(count));
}

__device__ __forceinline__ void mbar_expect_tx(uint32_t mbar, uint32_t bytes) {
    asm volatile("mbarrier.arrive.expect_tx.shared::cta.b64 _, [%0], %1;"
                 :: "r"(mbar), "r"(bytes) : "memory");
}

__device__ __forceinline__ void mbar_wait(uint32_t mbar, uint32_t parity) {
    asm volatile(
        "{\n\t"
        ".reg .pred P;\n\t"
        "WAIT_%=:\n\t"
        "mbarrier.try_wait.parity.acquire.cta.shared::cta.b64 P, [%0], %1, 0x989680;\n\t"
        "@P bra.uni DONE_%=;\n\t"
        "bra.uni WAIT_%=;\n\t"
        "DONE_%=:\n\t"
        "}"
        :: "r"(mbar), "r"(parity) : "memory");
}

// fp32 pair -> bf16x2 hi + bf16x2 lo (residual). lo half of reg = even elem.
__device__ __forceinline__ void cvt_hilo(float2 f, uint32_t &hi, uint32_t &lo) {
    asm("cvt.rn.bf16x2.f32 %0, %1, %2;" : "=r"(hi) : "f"(f.y), "f"(f.x));
    float rx = f.x - __uint_as_float(hi << 16);
    float ry = f.y - __uint_as_float(hi & 0xFFFF0000u);
    asm("cvt.rn.bf16x2.f32 %0, %1, %2;" : "=r"(lo) : "f"(ry), "f"(rx));
}

// m16n8k16 row.col bf16 HMMA, D=C in-place
__device__ __forceinline__ void mma_bf16(float *d, const uint32_t *a,
                                         const uint32_t *b) {
    asm volatile(
        "mma.sync.aligned.m16n8k16.row.col.f32.bf16.bf16.f32 "
        "{%0,%1,%2,%3}, {%4,%5,%6,%7}, {%8,%9}, {%0,%1,%2,%3};"
        : "+f"(d[0]), "+f"(d[1]), "+f"(d[2]), "+f"(d[3])
        : "r"(a[0]), "r"(a[1]), "r"(a[2]), "r"(a[3]), "r"(b[0]), "r"(b[1]));
}

// ---------------------------------------------------------------------------
// Kernel 1: conv 3x3 SAME + bias + relu + maxpool 2x2 (R13/R15 proven).
// ---------------------------------------------------------------------------
__global__ void __launch_bounds__(256) conv_pool_kernel(
    const float *__restrict__ x, const float *__restrict__ cw,
    const float *__restrict__ cb)
{
    __shared__ float sin_[3][34][34];
    __shared__ float wp[27 * 32];
    __shared__ float bb[32];

    int t = threadIdx.x;
    int b = blockIdx.y;
    int tpy = (blockIdx.x >> 2) * 16, tpx = (blockIdx.x & 3) * 16;

    for (int i = t; i < 864; i += 256) {
        int co = i / 27, rem = i % 27;
        wp[rem * 32 + co] = cw[i];
    }
    if (t < 32) bb[t] = cb[t];

    int oy = 2 * tpy - 1, ox = 2 * tpx - 1;
    for (int i = t; i < 3 * 34 * 34; i += 256) {
        int ci = i / 1156, rem = i % 1156, iy = rem / 34, ix = rem % 34;
        int gy = oy + iy, gx = ox + ix;
        float v = 0.f;
        if (gy >= 0 && gy < 128 && gx >= 0 && gx < 128)
            v = x[((b * 3 + ci) * 128 + gy) * 128 + gx];
        sin_[ci][iy][ix] = v;
    }
    __syncthreads();

    int py = t >> 4, px = t & 15;
    float in[3][4][4];
#pragma unroll
    for (int ci = 0; ci < 3; ci++)
#pragma unroll
        for (int r = 0; r < 4; r++)
#pragma unroll
            for (int c = 0; c < 4; c++)
                in[ci][r][c] = sin_[ci][2 * py + r][2 * px + c];

    const float2 *wp2 = reinterpret_cast<const float2 *>(wp);
    int gy = tpy + py, gx = tpx + px;
    float *outb = d_pool_buf + (size_t)b * 131072;

#pragma unroll
    for (int g = 0; g < 4; g++) {
        float2 acc[2][2][4];
#pragma unroll
        for (int dy = 0; dy < 2; dy++)
#pragma unroll
            for (int dx = 0; dx < 2; dx++)
#pragma unroll
                for (int p = 0; p < 4; p++) acc[dy][dx][p] = make_float2(0.f, 0.f);

#pragma unroll
        for (int ci = 0; ci < 3; ci++)
#pragma unroll
            for (int ky = 0; ky < 3; ky++)
#pragma unroll
                for (int kx = 0; kx < 3; kx++) {
                    int tap = ci * 9 + ky * 3 + kx;
                    float2 w0 = wp2[tap * 16 + g * 4 + 0];
                    float2 w1 = wp2[tap * 16 + g * 4 + 1];
                    float2 w2 = wp2[tap * 16 + g * 4 + 2];
                    float2 w3 = wp2[tap * 16 + g * 4 + 3];
#pragma unroll
                    for (int dy = 0; dy < 2; dy++)
#pragma unroll
                        for (int dx = 0; dx < 2; dx++) {
                            float iv = in[ci][dy + ky][dx + kx];
                            float2 iv2 = make_float2(iv, iv);
                            fma2(acc[dy][dx][0], iv2, w0);
                            fma2(acc[dy][dx][1], iv2, w1);
                            fma2(acc[dy][dx][2], iv2, w2);
                            fma2(acc[dy][dx][3], iv2, w3);
                        }
                }
#pragma unroll
        for (int p = 0; p < 4; p++) {
            int co = g * 8 + p * 2;
            float mx = fmaxf(fmaxf(acc[0][0][p].x, acc[0][1][p].x),
                             fmaxf(acc[1][0][p].x, acc[1][1][p].x));
            float my = fmaxf(fmaxf(acc[0][0][p].y, acc[0][1][p].y),
                             fmaxf(acc[1][0][p].y, acc[1][1][p].y));
            mx = fmaxf(mx + bb[co], 0.f);
            my = fmaxf(my + bb[co + 1], 0.f);
            outb[(co * 64 + gy) * 64 + gx] = mx;
            outb[((co + 1) * 64 + gy) * 64 + gx] = my;
        }
    }
}

// ---------------------------------------------------------------------------
// Kernel 2: GCN (R13/R15: node chunk 256, smem 45KB, 3 CTAs/SM). PDL wait
// before reading d_pool_buf.
// ---------------------------------------------------------------------------
__device__ __forceinline__ float dinvf(int r, int c) {
    int deg = 1 + (r > 0) + (r < 63) + (c > 0) + (c < 63);
    return rsqrtf((float)deg);
}

__global__ void __launch_bounds__(256) gcn_kernel(
    const float *__restrict__ gw, const float *__restrict__ gb)
{
    extern __shared__ float sm[];
    float *aggx = sm;            // [256][36]
    float *wg = sm + 256 * 36;   // [32][64]
    float *bg = wg + 2048;       // [64]

    int t = threadIdx.x, b = blockIdx.y;
    int node0 = blockIdx.x * 256;

    for (int i = t; i < 2048; i += 256) wg[i] = gw[i];
    if (t < 64) bg[t] = gb[t];

    grid_dep_wait();  // d_pool_buf produced by conv

    const float *nf = d_pool_buf + (size_t)b * 131072;
    int q = t & 7, ns = t >> 3;
#pragma unroll 4
    for (int i = 0; i < 8; i++) {
        int nl = ns + 32 * i;
        int n = node0 + nl;
        int r = n >> 6, c = n & 63;
        float dn = dinvf(r, c);
        const float4 *base = reinterpret_cast<const float4 *>(nf) + n * 8 + q;
        float4 v = __ldg(base);
        float4 a;
        a.x = dn * v.x; a.y = dn * v.y; a.z = dn * v.z; a.w = dn * v.w;
        if (r > 0) {
            float s = dinvf(r - 1, c); float4 u = __ldg(base - 512);
            a.x += s * u.x; a.y += s * u.y; a.z += s * u.z; a.w += s * u.w;
        }
        if (r < 63) {
            float s = dinvf(r + 1, c); float4 u = __ldg(base + 512);
            a.x += s * u.x; a.y += s * u.y; a.z += s * u.z; a.w += s * u.w;
        }
        if (c > 0) {
            float s = dinvf(r, c - 1); float4 u = __ldg(base - 8);
            a.x += s * u.x; a.y += s * u.y; a.z += s * u.z; a.w += s * u.w;
        }
        if (c < 63) {
            float s = dinvf(r, c + 1); float4 u = __ldg(base + 8);
            a.x += s * u.x; a.y += s * u.y; a.z += s * u.z; a.w += s * u.w;
        }
        a.x *= dn; a.y *= dn; a.z *= dn; a.w *= dn;
        *reinterpret_cast<float4 *>(&aggx[nl * 36 + q * 4]) = a;
    }
    __syncthreads();

    int ot = t & 7, ng = t >> 3;
    const float4 *wg4 = reinterpret_cast<const float4 *>(wg);
    uint32_t *ghi = reinterpret_cast<uint32_t *>(d_g_hi) + (size_t)b * 131072;
    uint32_t *glo = reinterpret_cast<uint32_t *>(d_g_lo) + (size_t)b * 131072;

    for (int it = 0; it < 2; it++) {
        int nb = (it * 32 + ng) * 4;
        float2 acc[4][4];
#pragma unroll
        for (int i = 0; i < 4; i++)
#pragma unroll
            for (int p = 0; p < 4; p++) acc[i][p] = make_float2(0.f, 0.f);

#pragma unroll 4
        for (int f = 0; f < 32; f++) {
            float4 wA = wg4[f * 16 + ot * 2];
            float4 wB = wg4[f * 16 + ot * 2 + 1];
            float2 p0 = make_float2(wA.x, wA.y), p1 = make_float2(wA.z, wA.w);
            float2 p2 = make_float2(wB.x, wB.y), p3 = make_float2(wB.z, wB.w);
#pragma unroll
            for (int i = 0; i < 4; i++) {
                float av = aggx[(nb + i) * 36 + f];
                float2 ad = make_float2(av, av);
                fma2(acc[i][0], ad, p0);
                fma2(acc[i][1], ad, p1);
                fma2(acc[i][2], ad, p2);
                fma2(acc[i][3], ad, p3);
            }
        }

#pragma unroll
        for (int i = 0; i < 4; i++) {
            int ubase = (node0 + nb + i) * 32 + ot * 4;
            uint4 H, L;
            float2 v;
            v.x = fmaxf(acc[i][0].x + bg[ot * 8 + 0], 0.f);
            v.y = fmaxf(acc[i][0].y + bg[ot * 8 + 1], 0.f);
            cvt_hilo(v, H.x, L.x);
            v.x = fmaxf(acc[i][1].x + bg[ot * 8 + 2], 0.f);
            v.y = fmaxf(acc[i][1].y + bg[ot * 8 + 3], 0.f);
            cvt_hilo(v, H.y, L.y);
            v.x = fmaxf(acc[i][2].x + bg[ot * 8 + 4], 0.f);
            v.y = fmaxf(acc[i][2].y + bg[ot * 8 + 5], 0.f);
            cvt_hilo(v, H.z, L.z);
            v.x = fmaxf(acc[i][3].x + bg[ot * 8 + 6], 0.f);
            v.y = fmaxf(acc[i][3].y + bg[ot * 8 + 7], 0.f);
            cvt_hilo(v, H.w, L.w);
            *reinterpret_cast<uint4 *>(ghi + ubase) = H;
            *reinterpret_cast<uint4 *>(glo + ubase) = L;
        }
    }
}

// ---------------------------------------------------------------------------
// Kernel 3: FC1 streaming HMMA GEMM (R15: slice 256, 1024 CTAs, unroll 8).
// PDL wait before staging G.
// ---------------------------------------------------------------------------
#define FC1_KSLICE 256
#define GROW_U32 132                     // uint32 words per padded G row (4 mod 32)
#define G_LO_OFF (32 * GROW_U32)         // uint32 offset of lo plane
#define FC1_SMEM (2 * 32 * GROW_U32 * 4 + 16)  // 33808 B

__global__ void __launch_bounds__(256) fc1_kernel(const float *__restrict__ w1)
{
    extern __shared__ uint32_t smg[];
    uint32_t sb = s2u(smg);
    uint32_t mb = sb + 2 * 32 * GROW_U32 * 4;
    int t = threadIdx.x, lane = t & 31, w = t >> 5;
    int bi = blockIdx.x;
    int kstart = bi * FC1_KSLICE;

    if (t == 0) mbar_init(mb, 32);
    __syncthreads();
    grid_dep_wait();  // d_g_hi/d_g_lo produced by gcn
    if (t < 32) {
        mbar_expect_tx(mb, 2 * FC1_KSLICE * 2);
        bulk_cp(sb + lane * (GROW_U32 * 4),
                d_g_hi + (size_t)lane * K_FC + kstart, FC1_KSLICE * 2, mb);
        bulk_cp(sb + G_LO_OFF * 4 + lane * (GROW_U32 * 4),
                d_g_lo + (size_t)lane * K_FC + kstart, FC1_KSLICE * 2, mb);
    }
    mbar_wait(mb, 0);

    float acc[4][4];
#pragma unroll
    for (int nt = 0; nt < 4; nt++)
#pragma unroll
        for (int p = 0; p < 4; p++) acc[nt][p] = 0.f;

    int q = lane >> 2, kc2 = lane & 3;   // fragment coords; kc = 2*kc2
    int mbase = 16 * w;
    const float *wb0 = w1 + (size_t)(mbase + q) * K_FC + kstart + kc2 * 2;
    const float *wb1 = wb0 + (size_t)8 * K_FC;

#pragma unroll 8
    for (int ks = 0; ks < FC1_KSLICE / 16; ks++) {
        float2 fa0 = __ldg(reinterpret_cast<const float2 *>(wb0 + ks * 16));
        float2 fa1 = __ldg(reinterpret_cast<const float2 *>(wb1 + ks * 16));
        float2 fa2 = __ldg(reinterpret_cast<const float2 *>(wb0 + ks * 16 + 8));
        float2 fa3 = __ldg(reinterpret_cast<const float2 *>(wb1 + ks * 16 + 8));
        uint32_t Ah[4], Al[4];
        cvt_hilo(fa0, Ah[0], Al[0]);
        cvt_hilo(fa1, Ah[1], Al[1]);
        cvt_hilo(fa2, Ah[2], Al[2]);
        cvt_hilo(fa3, Ah[3], Al[3]);

        int wq = ks * 8 + kc2;
#pragma unroll
        for (int nt = 0; nt < 4; nt++) {
            int n = nt * 8 + q;
            uint32_t bh[2], bl[2];
            bh[0] = smg[n * GROW_U32 + wq];
            bh[1] = smg[n * GROW_U32 + wq + 4];
            bl[0] = smg[G_LO_OFF + n * GROW_U32 + wq];
            bl[1] = smg[G_LO_OFF + n * GROW_U32 + wq + 4];
            mma_bf16(acc[nt], Ah, bh);
            mma_bf16(acc[nt], Ah, bl);
            mma_bf16(acc[nt], Al, bh);
        }
    }

    float *pp = d_part_buf + (size_t)bi * 4096;
    int cb = kc2 * 2;
#pragma unroll
    for (int nt = 0; nt < 4; nt++) {
        int n0 = nt * 8 + cb;
        pp[(n0    ) * 128 + mbase + q    ] = acc[nt][0];
        pp[(n0 + 1) * 128 + mbase + q    ] = acc[nt][1];
        pp[(n0    ) * 128 + mbase + q + 8] = acc[nt][2];
        pp[(n0 + 1) * 128 + mbase + q + 8] = acc[nt][3];
    }
}

// ---------------------------------------------------------------------------
// Kernel 4a: reduce 1024 partial sets -> relu(f1 + b1).  grid (32 b, 4 jq)
// (R15 version.) PDL wait before reading partials.
// ---------------------------------------------------------------------------
__global__ void __launch_bounds__(1024) fc1_reduce_kernel(const float *__restrict__ f1b)
{
    __shared__ float red[32][33];
    int t = threadIdx.x, b = blockIdx.x, jq = blockIdx.y;
    int jl = t & 31, sg = t >> 5;
    int j = jq * 32 + jl;

    grid_dep_wait();  // d_part_buf produced by fc1

    const float *pp = d_part_buf + b * 128 + j;
    float ssum = 0.f;
#pragma unroll 32
    for (int i = sg; i < 1024; i += 32) ssum += __ldg(&pp[(size_t)i * 4096]);
    red[sg][jl] = ssum;
    __syncthreads();

    if (t < 32) {
        float v = 0.f;
#pragma unroll
        for (int u = 0; u < 32; u++) v += red[u][t];
        int jo = jq * 32 + t;
        d_f1_buf[b * 128 + jo] = fmaxf(v + f1b[jo], 0.f);
    }
}

// ---------------------------------------------------------------------------
// Kernel 4b: FC2 (101 x 128) + bias.  grid 32. PDL wait before reading f1.
// ---------------------------------------------------------------------------
__global__ void __launch_bounds__(128) fc2_kernel(
    const float *__restrict__ w2, const float *__restrict__ b2,
    float *__restrict__ out)
{
    __shared__ float f1s[128];
    int t = threadIdx.x, b = blockIdx.x;
    grid_dep_wait();  // d_f1_buf produced by reduce
    f1s[t] = d_f1_buf[b * 128 + t];
    __syncthreads();

    if (t < 101) {
        float acc = b2[t];
        const float *wr = w2 + t * 128;
#pragma unroll 8
        for (int jj = 0; jj < 128; jj++) acc = fmaf(f1s[jj], __ldg(&wr[jj]), acc);
        out[b * 101 + t] = acc;
    }
}

// ---------------------------------------------------------------------------
// Launch helper: cudaLaunchKernelEx with programmatic stream serialization.
// ---------------------------------------------------------------------------
template <typename K, typename... Args>
static void launch_pdl(dim3 grid, dim3 block, int smem, K kernel, Args... args)
{
    cudaLaunchConfig_t cfg = {};
    cfg.gridDim = grid;
    cfg.blockDim = block;
    cfg.dynamicSmemBytes = (size_t)smem;
    cfg.stream = 0;
    cudaLaunchAttribute attr[1];
    attr[0].id = cudaLaunchAttributeProgrammaticStreamSerialization;
    attr[0].val.programmaticStreamSerializationAllowed = 1;
    cfg.attrs = attr;
    cfg.numAttrs = 1;
    cudaLaunchKernelEx(&cfg, kernel, args...);
}

extern "C" void kernel_launch(void *const *d_in, const int *in_sizes, int n_in,
                              void *d_out, int out_size)
{
    (void)in_sizes; (void)n_in; (void)out_size;
    const float *x  = (const float *)d_in[0];
    const float *cw = (const float *)d_in[1];
    const float *cb = (const float *)d_in[2];
    const float *gw = (const float *)d_in[3];
    const float *gb = (const float *)d_in[4];
    const float *w1 = (const float *)d_in[5];
    const float *b1 = (const float *)d_in[6];
    const float *w2 = (const float *)d_in[7];
    const float *b2 = (const float *)d_in[8];
    float *out = (float *)d_out;

    const int gcn_smem = (256 * 36 + 2048 + 64) * 4;  // 45312 B
    cudaFuncSetAttribute(gcn_kernel, cudaFuncAttributeMaxDynamicSharedMemorySize, gcn_smem);
    cudaFuncSetAttribute(fc1_kernel, cudaFuncAttributeMaxDynamicSharedMemorySize, FC1_SMEM);

    conv_pool_kernel<<<dim3(16, 32), 256>>>(x, cw, cb);               // launch 1
    launch_pdl(dim3(16, 32), dim3(256), gcn_smem, gcn_kernel, gw, gb);    // 2
    launch_pdl(dim3(1024), dim3(256), FC1_SMEM, fc1_kernel, w1);          // 3
    launch_pdl(dim3(32, 4), dim3(1024), 0, fc1_reduce_kernel, b1);        // 4
    launch_pdl(dim3(32), dim3(128), 0, fc2_kernel, w2, b2, out);          // 5
}